// round 15
// baseline (speedup 1.0000x reference)
#include <cuda_runtime.h>
#include <cuda_fp16.h>
#include <cstdint>

#define B_TOT 1024
#define T_LEN 512
#define NU 64
#define NBR 4            // real batch rows per CTA (n-tile padded to 8)
#define NCTA (B_TOT / NBR)
#define THR 256

__device__ float g_h[(size_t)B_TOT * T_LEN * NU];

__device__ __forceinline__ float sigf(float x) {
    float t; asm("tanh.approx.f32 %0, %1;" : "=f"(t) : "f"(0.5f * x));
    return fmaf(0.5f, t, 0.5f);
}
__device__ __forceinline__ uint32_t pack_h2(__half a, __half b) {
    __half2 p; p.x = a; p.y = b; return *(uint32_t*)&p;
}
__device__ __forceinline__ void hmma(float* c, const uint32_t* a, uint32_t b0, uint32_t b1) {
    asm volatile("mma.sync.aligned.m16n8k16.row.col.f32.f16.f16.f32 "
        "{%0,%1,%2,%3}, {%4,%5,%6,%7}, {%8,%9}, {%0,%1,%2,%3};"
        : "+f"(c[0]), "+f"(c[1]), "+f"(c[2]), "+f"(c[3])
        : "r"(a[0]), "r"(a[1]), "r"(a[2]), "r"(a[3]), "r"(b0), "r"(b1));
}

// 256 CTAs x 4 batch rows (2 CTAs/SM): 8 warps/CTA, warp w owns gate-cols
// [32w,32w+32) = 2 m16 tiles (units [8w,8w+4) and [8w+4,8w+8), all gates).
// n-tile = 8 rows, rows 4..7 zero-padded (garbage cells predicated off).
// fp16 2-term: z = Whi*Ahi + Whi*Alo. Tiles share B-fragments. Per-lane
// epilogue handles 2 cells (one per tile). 1 __syncthreads per step.
template <int KX, bool LAST>
__global__ void __launch_bounds__(THR, 2)
lstm_layer(const float* __restrict__ xin, const float* __restrict__ Wx,
           const float* __restrict__ U,   const float* __restrict__ bias)
{
    constexpr int KTOT = KX + NU;       // 128 or 64
    constexpr int KS   = KTOT / 16;     // 8 or 4
    constexpr int P    = 2 * KTOT + 8;  // fp16 pitch: hi block | lo block

    __shared__ __half act[2][8 * P];    // 8 n-rows (4 real, 4 zero)
    __shared__ float Xsh[2][NBR];

    const int tid  = threadIdx.x;
    const int wid  = tid >> 5;          // 0..7
    const int lane = tid & 31;
    const int lr   = lane >> 2;
    const int qq   = lane & 3;
    const int aa   = lr >> 2;
    const int gg   = lr & 3;
    const int bg0  = blockIdx.x * NBR;

    const int ul = aa + 2 * (gg >> 1);
    const int b  = 2 * qq + (gg & 1);   // 0..7; real cell iff b < 4
    const int u0 = 8 * wid + ul;        // tile0 cell unit
    const int u1 = u0 + 4;              // tile1 cell unit
    const int eb = tid >> 6;            // 0..3 (x-part staging row)
    const int eu = tid & 63;

    // ---- W fragments: tile tau, gate-interleaved cols ----
    uint32_t Whi[KS][2][4];
    #pragma unroll
    for (int s = 0; s < KS; ++s) {
        #pragma unroll
        for (int tau = 0; tau < 2; ++tau) {
            #pragma unroll
            for (int i = 0; i < 4; ++i) {
                const int k = 16 * s + 2 * qq + ((i >> 1) << 3);
                const int m = 32 * wid + 16 * tau + lr + ((i & 1) << 3);
                const int oc = (m >> 2) + 64 * (m & 3);
                float f0 = (k < KX) ? Wx[(size_t)k * 256 + oc]
                                    : U[(size_t)(k - KX) * 256 + oc];
                float f1 = (k + 1 < KX) ? Wx[(size_t)(k + 1) * 256 + oc]
                                        : U[(size_t)(k + 1 - KX) * 256 + oc];
                Whi[s][tau][i] = pack_h2(__float2half(f0), __float2half(f1));
            }
        }
    }
    float bg2[2][4], wxg2[2][4];
    #pragma unroll
    for (int g = 0; g < 4; ++g) {
        bg2[0][g] = bias[u0 + 64 * g];
        bg2[1][g] = bias[u1 + 64 * g];
        wxg2[0][g] = (KX == 0) ? Wx[u0 + 64 * g] : 0.0f;
        wxg2[1][g] = (KX == 0) ? Wx[u1 + 64 * g] : 0.0f;
    }

    for (int i = tid; i < 2 * 8 * P; i += THR) act[0][i] = __float2half(0.0f);

    // ---- stage step-0 input (x-part rows 0..3) ----
    float cs0 = 0.0f, cs1 = 0.0f;
    if (KX == 0) {
        if (tid < NBR) Xsh[0][tid] = xin[(size_t)(bg0 + tid) * T_LEN + 0];
    } else {
        float v0 = g_h[((size_t)(bg0 + eb) * T_LEN + 0) * NU + eu];
        __half xh = __float2half(v0);
        act[0][eb * P + eu]        = xh;
        act[0][eb * P + KTOT + eu] = __float2half(v0 - __half2float(xh));
    }

    for (int t = 0; t < T_LEN; ++t) {
        const int p = t & 1;
        __syncthreads();   // buf[p] complete

        // prefetch step t+1 x-part (hidden under MMA)
        const int tn = (t + 1 < T_LEN) ? t + 1 : T_LEN - 1;
        float vn = 0.0f, xvn = 0.0f;
        if (KX == 0) {
            if (tid < NBR) xvn = xin[(size_t)(bg0 + tid) * T_LEN + tn];
        } else {
            vn = g_h[((size_t)(bg0 + eb) * T_LEN + tn) * NU + eu];
        }

        // ---- MMA: 2 tiles x 2 terms x KS; B-frags shared across tiles ----
        float acc[2][2][4];
        #pragma unroll
        for (int tau = 0; tau < 2; ++tau)
            #pragma unroll
            for (int c = 0; c < 2; ++c)
                acc[tau][c][0] = acc[tau][c][1] = acc[tau][c][2] = acc[tau][c][3] = 0.0f;
        const __half* ap = act[p];
        #pragma unroll
        for (int s = 0; s < KS; ++s) {
            const uint32_t* bp = (const uint32_t*)(ap + lr * P + 16 * s + 2 * qq);
            const uint32_t b0h = bp[0], b1h = bp[4];
            const uint32_t b0l = bp[KTOT / 2], b1l = bp[KTOT / 2 + 4];
            hmma(acc[0][s & 1], Whi[s][0], b0h, b1h);
            hmma(acc[0][s & 1], Whi[s][0], b0l, b1l);
            hmma(acc[1][s & 1], Whi[s][1], b0h, b1h);
            hmma(acc[1][s & 1], Whi[s][1], b0l, b1l);
        }

        __half* an = act[p ^ 1];
        #pragma unroll
        for (int tau = 0; tau < 2; ++tau) {
            float z0 = acc[tau][0][0] + acc[tau][1][0];
            float z1 = acc[tau][0][1] + acc[tau][1][1];
            float z2 = acc[tau][0][2] + acc[tau][1][2];
            float z3 = acc[tau][0][3] + acc[tau][1][3];
            { // 4x4 lane transpose over lane bits 2-3
                const bool g0 = (lane & 4), g1 = (lane & 8);
                float sA = g0 ? z0 : z1, sB = g0 ? z2 : z3;
                float tA = __shfl_xor_sync(~0u, sA, 4), tB = __shfl_xor_sync(~0u, sB, 4);
                if (!g0) { z1 = tA; z3 = tB; } else { z0 = tA; z2 = tB; }
                float sC = g1 ? z0 : z2, sD = g1 ? z1 : z3;
                float tC = __shfl_xor_sync(~0u, sC, 8), tD = __shfl_xor_sync(~0u, sD, 8);
                if (!g1) { z2 = tC; z3 = tD; } else { z0 = tC; z1 = tD; }
            }
            float zi = z0 + bg2[tau][0], zf = z1 + bg2[tau][1];
            float zg = z2 + bg2[tau][2], zo = z3 + bg2[tau][3];
            if (KX == 0) {
                float xr = (b < NBR) ? Xsh[p][b] : 0.0f;
                zi = fmaf(xr, wxg2[tau][0], zi); zf = fmaf(xr, wxg2[tau][1], zf);
                zg = fmaf(xr, wxg2[tau][2], zg); zo = fmaf(xr, wxg2[tau][3], zo);
            }
            float cprev = tau ? cs1 : cs0;
            float cn = fmaf(sigf(zf), cprev, sigf(zi) * fmaxf(zg, 0.0f));
            if (tau) cs1 = cn; else cs0 = cn;
            float h = sigf(zo) * fmaxf(cn, 0.0f);
            if (b < NBR) {
                const int u = tau ? u1 : u0;
                __half hh = __float2half(h);
                an[b * P + KX + u]        = hh;
                an[b * P + KTOT + KX + u] = __float2half(h - __half2float(hh));
                if (!LAST || t == T_LEN - 1)
                    g_h[((size_t)(bg0 + b) * T_LEN + t) * NU + u] = h;
            }
        }
        // stage next x-part
        if (KX == 0) {
            if (tid < NBR) Xsh[p ^ 1][tid] = xvn;
        } else {
            __half xh = __float2half(vn);
            an[eb * P + eu]        = xh;
            an[eb * P + KTOT + eu] = __float2half(vn - __half2float(xh));
        }
    }
}

__global__ void __launch_bounds__(256)
head_kernel(const float* __restrict__ Wd, const float* __restrict__ bd,
            float* __restrict__ out)
{
    __shared__ float wd[NU];
    if (threadIdx.x < NU) wd[threadIdx.x] = Wd[threadIdx.x];
    __syncthreads();
    int b = blockIdx.x * blockDim.x + threadIdx.x;
    const float* hp = g_h + ((size_t)b * T_LEN + (T_LEN - 1)) * NU;
    float s = 0.0f;
    #pragma unroll
    for (int u = 0; u < NU; ++u) s += hp[u] * wd[u];
    out[b] = s + bd[0];
}

extern "C" void kernel_launch(void* const* d_in, const int* in_sizes, int n_in,
                              void* d_out, int out_size)
{
    const float* x   = (const float*)d_in[0];
    const float* Wx0 = (const float*)d_in[1];
    const float* U0  = (const float*)d_in[2];
    const float* b0  = (const float*)d_in[3];
    const float* Wx1 = (const float*)d_in[4];
    const float* U1  = (const float*)d_in[5];
    const float* b1  = (const float*)d_in[6];
    const float* Wx2 = (const float*)d_in[7];
    const float* U2  = (const float*)d_in[8];
    const float* b2  = (const float*)d_in[9];
    const float* Wx3 = (const float*)d_in[10];
    const float* U3  = (const float*)d_in[11];
    const float* b3  = (const float*)d_in[12];
    const float* Wd  = (const float*)d_in[13];
    const float* bd  = (const float*)d_in[14];
    float* out = (float*)d_out;

    lstm_layer<0,  false><<<NCTA, THR>>>(x,       Wx0, U0, b0);
    lstm_layer<64, false><<<NCTA, THR>>>(nullptr, Wx1, U1, b1);
    lstm_layer<64, false><<<NCTA, THR>>>(nullptr, Wx2, U2, b2);
    lstm_layer<64, true ><<<NCTA, THR>>>(nullptr, Wx3, U3, b3);
    head_kernel<<<B_TOT / 256, 256>>>(Wd, bd, out);
}

// round 16
// speedup vs baseline: 1.6033x; 1.6033x over previous
#include <cuda_runtime.h>
#include <cuda_fp16.h>
#include <cstdint>

#define B_TOT 1024
#define T_LEN 512
#define NU 64
#define NB 8
#define NCTA 128
#define THR 256

__device__ float g_h[(size_t)B_TOT * T_LEN * NU];

__device__ __forceinline__ float sigf(float x) {
    float t; asm("tanh.approx.f32 %0, %1;" : "=f"(t) : "f"(0.5f * x));
    return fmaf(0.5f, t, 0.5f);
}
__device__ __forceinline__ uint32_t pack_h2(__half a, __half b) {
    __half2 p; p.x = a; p.y = b; return *(uint32_t*)&p;
}
__device__ __forceinline__ void hmma(float* c, const uint32_t* a, uint32_t b0, uint32_t b1) {
    asm volatile("mma.sync.aligned.m16n8k16.row.col.f32.f16.f16.f32 "
        "{%0,%1,%2,%3}, {%4,%5,%6,%7}, {%8,%9}, {%0,%1,%2,%3};"
        : "+f"(c[0]), "+f"(c[1]), "+f"(c[2]), "+f"(c[3])
        : "r"(a[0]), "r"(a[1]), "r"(a[2]), "r"(a[3]), "r"(b0), "r"(b1));
}

// 8 warps/CTA, 128 CTAs x 8 batch rows. Warp w owns units [8w,8w+8):
//   tile0: m rows 0-7 = gate i, rows 8-15 = gate f  (of units 8w+0..7)
//   tile1: m rows 0-7 = gate g, rows 8-15 = gate o
// => after MMA each lane holds ALL 4 gates of cells (u=8w+lr, b=2qq{,+1})
//    in registers -- no shuffle transpose.
// k-split pipeline: x-part (k<KX, prev-layer h) of step t+1 is MMA'd at the
// END of step t (off the critical path, carried in zx regs); the critical
// chain per step is only bar -> LDS h-frags -> 16 HMMA -> epilogue -> STS.
// fp16 2-term: z = Whi*Ahi + Whi*Alo (act hi/lo split).
template <int KX, bool LAST>
__global__ void __launch_bounds__(THR)
lstm_layer(const float* __restrict__ xin, const float* __restrict__ Wx,
           const float* __restrict__ U,   const float* __restrict__ bias)
{
    constexpr int KTOT = KX + NU;       // 128 or 64
    constexpr int KS   = KTOT / 16;     // 8 or 4
    constexpr int KSX  = KX / 16;       // 4 or 0
    constexpr int KSH  = NU / 16;       // 4
    constexpr int P    = 2 * KTOT + 8;  // fp16 pitch: hi block | lo block

    __shared__ __half act[2][NB * P];
    __shared__ float Xsh[2][NB];

    const int tid  = threadIdx.x;
    const int wid  = tid >> 5;          // 0..7
    const int lane = tid & 31;
    const int lr   = lane >> 2;
    const int qq   = lane & 3;
    const int bg0  = blockIdx.x * NB;
    const int u    = 8 * wid + lr;      // owned unit (both cells)
    const int bA   = 2 * qq;            // cell batches bA, bA+1
    const int sb   = wid;               // staging row
    const int su   = lane;              // staging units su, su+32

    // ---- W fragments: tile tau = gates (2tau, 2tau+1) of unit u ----
    uint32_t Wf[KS][2][4];
    #pragma unroll
    for (int s = 0; s < KS; ++s)
        #pragma unroll
        for (int tau = 0; tau < 2; ++tau)
            #pragma unroll
            for (int i = 0; i < 4; ++i) {
                const int k = 16 * s + 2 * qq + ((i >> 1) << 3);
                const int oc = u + 64 * (2 * tau + (i & 1));
                float f0 = (k < KX) ? Wx[(size_t)k * 256 + oc]
                                    : U[(size_t)(k - KX) * 256 + oc];
                float f1 = (k + 1 < KX) ? Wx[(size_t)(k + 1) * 256 + oc]
                                        : U[(size_t)(k + 1 - KX) * 256 + oc];
                Wf[s][tau][i] = pack_h2(__float2half(f0), __float2half(f1));
            }
    float bg[4], wxg[4];
    #pragma unroll
    for (int g = 0; g < 4; ++g) {
        bg[g]  = bias[u + 64 * g];
        wxg[g] = (KX == 0) ? Wx[u + 64 * g] : 0.0f;
    }

    for (int i = tid; i < 2 * NB * P; i += THR) (&act[0][0])[i] = __float2half(0.0f);

    // ---- stage x(0), prefetch x(1) ----
    float xn0 = 0.0f, xn1 = 0.0f, xs = 0.0f;
    if (KX == 0) {
        if (tid < NB) {
            Xsh[0][tid] = xin[(size_t)(bg0 + tid) * T_LEN + 0];
            xs = xin[(size_t)(bg0 + tid) * T_LEN + 1];
        }
    } else {
        float v0 = g_h[((size_t)(bg0 + sb) * T_LEN + 0) * NU + su];
        float v1 = g_h[((size_t)(bg0 + sb) * T_LEN + 0) * NU + su + 32];
        __half h0 = __float2half(v0), h1 = __float2half(v1);
        act[0][sb * P + su]             = h0;
        act[0][sb * P + KTOT + su]      = __float2half(v0 - __half2float(h0));
        act[0][sb * P + su + 32]        = h1;
        act[0][sb * P + KTOT + su + 32] = __float2half(v1 - __half2float(h1));
        xn0 = g_h[((size_t)(bg0 + sb) * T_LEN + 1) * NU + su];
        xn1 = g_h[((size_t)(bg0 + sb) * T_LEN + 1) * NU + su + 32];
    }
    __syncthreads();

    // ---- zx for step 0 ----
    float zx[2][4] = {{0, 0, 0, 0}, {0, 0, 0, 0}};
    if (KX) {
        const __half* ap = act[0];
        #pragma unroll
        for (int s = 0; s < KSX; ++s) {
            const uint32_t* bp = (const uint32_t*)(ap + lr * P + 16 * s + 2 * qq);
            uint32_t b0 = bp[0], b1 = bp[4], b2 = bp[KTOT / 2], b3 = bp[KTOT / 2 + 4];
            hmma(zx[0], Wf[s][0], b0, b1); hmma(zx[0], Wf[s][0], b2, b3);
            hmma(zx[1], Wf[s][1], b0, b1); hmma(zx[1], Wf[s][1], b2, b3);
        }
    }

    float cs[2] = {0.0f, 0.0f};

    for (int t = 0; t < T_LEN; ++t) {
        const int p = t & 1;
        const __half* ap = act[p];
        __half* an = act[p ^ 1];

        // (1) critical: load h-frags of buf p
        uint32_t hf[KSH][4];
        #pragma unroll
        for (int s2 = 0; s2 < KSH; ++s2) {
            const uint32_t* bp =
                (const uint32_t*)(ap + lr * P + 16 * (KSX + s2) + 2 * qq);
            hf[s2][0] = bp[0]; hf[s2][1] = bp[4];
            hf[s2][2] = bp[KTOT / 2]; hf[s2][3] = bp[KTOT / 2 + 4];
        }

        // (2) stage x(t+1) into buf p^1; prefetch x(t+2)  (off critical path)
        const int tn2 = (t + 2 < T_LEN) ? t + 2 : T_LEN - 1;
        if (KX == 0) {
            if (tid < NB) {
                Xsh[p ^ 1][tid] = xs;
                xs = xin[(size_t)(bg0 + tid) * T_LEN + tn2];
            }
        } else {
            __half h0 = __float2half(xn0), h1 = __float2half(xn1);
            an[sb * P + su]             = h0;
            an[sb * P + KTOT + su]      = __float2half(xn0 - __half2float(h0));
            an[sb * P + su + 32]        = h1;
            an[sb * P + KTOT + su + 32] = __float2half(xn1 - __half2float(h1));
            xn0 = g_h[((size_t)(bg0 + sb) * T_LEN + tn2) * NU + su];
            xn1 = g_h[((size_t)(bg0 + sb) * T_LEN + tn2) * NU + su + 32];
        }

        // (3) critical: h-MMA (16 HMMA, 2 chains per tile)
        float zh[2][2][4] = {};
        #pragma unroll
        for (int s2 = 0; s2 < KSH; ++s2) {
            #pragma unroll
            for (int tau = 0; tau < 2; ++tau) {
                float* a = zh[tau][s2 & 1];
                hmma(a, Wf[KSX + s2][tau], hf[s2][0], hf[s2][1]);
                hmma(a, Wf[KSX + s2][tau], hf[s2][2], hf[s2][3]);
            }
        }

        // (4) epilogue: 2 cells, gates already lane-local (no shuffles)
        #pragma unroll
        for (int cj = 0; cj < 2; ++cj) {
            float zi = zh[0][0][cj]     + zh[0][1][cj]     + bg[0];
            float zf = zh[0][0][cj + 2] + zh[0][1][cj + 2] + bg[1];
            float zg = zh[1][0][cj]     + zh[1][1][cj]     + bg[2];
            float zo = zh[1][0][cj + 2] + zh[1][1][cj + 2] + bg[3];
            if (KX) {
                zi += zx[0][cj]; zf += zx[0][cj + 2];
                zg += zx[1][cj]; zo += zx[1][cj + 2];
            } else {
                float xr = Xsh[p][bA + cj];
                zi = fmaf(xr, wxg[0], zi); zf = fmaf(xr, wxg[1], zf);
                zg = fmaf(xr, wxg[2], zg); zo = fmaf(xr, wxg[3], zo);
            }
            float cn = fmaf(sigf(zf), cs[cj], sigf(zi) * fmaxf(zg, 0.0f));
            cs[cj] = cn;
            float h = sigf(zo) * fmaxf(cn, 0.0f);
            const int b = bA + cj;
            __half hh = __float2half(h);
            an[b * P + KX + u]        = hh;
            an[b * P + KTOT + KX + u] = __float2half(h - __half2float(hh));
            if (!LAST || t == T_LEN - 1)
                g_h[((size_t)(bg0 + b) * T_LEN + t) * NU + u] = h;
        }
        __syncthreads();   // publishes buf p^1 (h + x parts)

        // (5) x-MMA for step t+1 (independent of h(t+1) chain)
        if (KX && t + 1 < T_LEN) {
            #pragma unroll
            for (int tau = 0; tau < 2; ++tau)
                #pragma unroll
                for (int c = 0; c < 4; ++c) zx[tau][c] = 0.0f;
            #pragma unroll
            for (int s = 0; s < KSX; ++s) {
                const uint32_t* bp =
                    (const uint32_t*)(an + lr * P + 16 * s + 2 * qq);
                uint32_t b0 = bp[0], b1 = bp[4];
                uint32_t b2 = bp[KTOT / 2], b3 = bp[KTOT / 2 + 4];
                hmma(zx[0], Wf[s][0], b0, b1); hmma(zx[0], Wf[s][0], b2, b3);
                hmma(zx[1], Wf[s][1], b0, b1); hmma(zx[1], Wf[s][1], b2, b3);
            }
        }
    }
}

__global__ void __launch_bounds__(256)
head_kernel(const float* __restrict__ Wd, const float* __restrict__ bd,
            float* __restrict__ out)
{
    __shared__ float wd[NU];
    if (threadIdx.x < NU) wd[threadIdx.x] = Wd[threadIdx.x];
    __syncthreads();
    int b = blockIdx.x * blockDim.x + threadIdx.x;
    const float* hp = g_h + ((size_t)b * T_LEN + (T_LEN - 1)) * NU;
    float s = 0.0f;
    #pragma unroll
    for (int u = 0; u < NU; ++u) s += hp[u] * wd[u];
    out[b] = s + bd[0];
}

extern "C" void kernel_launch(void* const* d_in, const int* in_sizes, int n_in,
                              void* d_out, int out_size)
{
    const float* x   = (const float*)d_in[0];
    const float* Wx0 = (const float*)d_in[1];
    const float* U0  = (const float*)d_in[2];
    const float* b0  = (const float*)d_in[3];
    const float* Wx1 = (const float*)d_in[4];
    const float* U1  = (const float*)d_in[5];
    const float* b1  = (const float*)d_in[6];
    const float* Wx2 = (const float*)d_in[7];
    const float* U2  = (const float*)d_in[8];
    const float* b2  = (const float*)d_in[9];
    const float* Wx3 = (const float*)d_in[10];
    const float* U3  = (const float*)d_in[11];
    const float* b3  = (const float*)d_in[12];
    const float* Wd  = (const float*)d_in[13];
    const float* bd  = (const float*)d_in[14];
    float* out = (float*)d_out;

    lstm_layer<0,  false><<<NCTA, THR>>>(x,       Wx0, U0, b0);
    lstm_layer<64, false><<<NCTA, THR>>>(nullptr, Wx1, U1, b1);
    lstm_layer<64, false><<<NCTA, THR>>>(nullptr, Wx2, U2, b2);
    lstm_layer<64, true ><<<NCTA, THR>>>(nullptr, Wx3, U3, b3);
    head_kernel<<<B_TOT / 256, 256>>>(Wd, bd, out);
}